// round 6
// baseline (speedup 1.0000x reference)
#include <cuda_runtime.h>
#include <math.h>

#define NPIX 16384
#define BN   65536   // 4 * 16384

typedef unsigned long long u64;

// ------------ scratch ------------------------------------------------------
__device__ float g_k[64*BN];
__device__ float g_v[64*BN];
__device__ float g_q[64*BN];
__device__ float g_xm[64*BN];
__device__ float g_u[128*BN];          // LN staging (L2-resident)
__device__ float g_Gpart[4*128*1024];
__device__ float g_sqp[4*128*64];
__device__ float g_skp[4*128*64];
__device__ float g_A[4096];
__device__ float g_weffT[4*4096];
__device__ float g_wcatT[4096];
__device__ float g_inwT[4096];
__device__ float g_wkT[4096];
__device__ float g_wvT[4096];
__device__ float g_wqT[4096];
__device__ float g_w1T[8192];
__device__ float g_w2T[16384];
__device__ float g_bcat[64];

// ------------ f32x2 helpers --------------------------------------------------
__device__ __forceinline__ u64 pack2(float lo, float hi){
    u64 r; asm("mov.b64 %0, {%1,%2};" : "=l"(r) : "f"(lo), "f"(hi)); return r;
}
__device__ __forceinline__ void unpack2(u64 a, float& lo, float& hi){
    asm("mov.b64 {%0,%1}, %2;" : "=f"(lo), "=f"(hi) : "l"(a));
}
__device__ __forceinline__ u64 fma2_(u64 a, u64 b, u64 c){
    u64 d; asm("fma.rn.f32x2 %0, %1, %2, %3;" : "=l"(d) : "l"(a), "l"(b), "l"(c)); return d;
}
__device__ __forceinline__ u64 add2_(u64 a, u64 b){
    u64 d; asm("add.rn.f32x2 %0, %1, %2;" : "=l"(d) : "l"(a), "l"(b)); return d;
}
__device__ __forceinline__ float hadd2(u64 a){
    float lo, hi; unpack2(a, lo, hi); return lo + hi;
}

__device__ __forceinline__ float dot64p(const float* w, const u64* xp){
    const ulonglong2* w2 = (const ulonglong2*)w;
    u64 a0=0ull,a1=0ull,a2=0ull,a3=0ull;
    #pragma unroll
    for (int i=0;i<8;i++){
        ulonglong2 wa=w2[2*i], wb=w2[2*i+1];
        a0=fma2_(xp[4*i+0], wa.x, a0);
        a1=fma2_(xp[4*i+1], wa.y, a1);
        a2=fma2_(xp[4*i+2], wb.x, a2);
        a3=fma2_(xp[4*i+3], wb.y, a3);
    }
    return hadd2(add2_(add2_(a0,a1),add2_(a2,a3)));
}
__device__ __forceinline__ float dot128p(const float* w, const u64* xp){
    const ulonglong2* w2 = (const ulonglong2*)w;
    u64 a0=0ull,a1=0ull,a2=0ull,a3=0ull;
    #pragma unroll
    for (int i=0;i<16;i++){
        ulonglong2 wa=w2[2*i], wb=w2[2*i+1];
        a0=fma2_(xp[4*i+0], wa.x, a0);
        a1=fma2_(xp[4*i+1], wa.y, a1);
        a2=fma2_(xp[4*i+2], wb.x, a2);
        a3=fma2_(xp[4*i+3], wb.y, a3);
    }
    return hadd2(add2_(add2_(a0,a1),add2_(a2,a3)));
}

// ------------ kprep ----------------------------------------------------------
__global__ void kprep(const float* wa, const float* ba, const float* wb, const float* bb,
                      const float* inw, const float* wk, const float* wv, const float* wq,
                      const float* w1, const float* w2)
{
    int t = blockIdx.x*256 + threadIdx.x;     // 0..16383
    if (t < 4096) {
        int j = t>>6, c = t&63;
        float w;
        if (j < 4) w = wa[c*4 + j];
        else { int u=j-4; int kk=u/3; int d=u-kk*3; w = wb[kk*192 + c*3 + d]; }
        g_wcatT[t] = w;
        g_inwT[t]  = inw[c*64 + j];
        g_wkT[t]   = wk[c*64 + j];
        g_wvT[t]   = wv[c*64 + j];
        g_wqT[t]   = wq[c*64 + j];
    }
    if (t < 8192)  { int o=t>>6, c=t&63;  g_w1T[t] = w1[c*128 + o]; }
    if (t < 16384) { int o=t>>7, i=t&127; g_w2T[t] = w2[i*128 + o]; }
    if (t < 64) g_bcat[t] = (t < 4) ? ba[t] : bb[t-4];
}

// ------------ k1: feat path -> y -> k, v  (128 thr, 3 CTA/SM) ----------------
// dyn smem floats: s_w 8192 | s_sem 2688 | s_bias 256  => 44544 B
__global__ void __launch_bounds__(128,3)
k1(const float* __restrict__ x, const float* __restrict__ sem,
   const float* __restrict__ inb, const float* __restrict__ bk, const float* __restrict__ bv)
{
    extern __shared__ float smx[];
    float* s_w    = smx;            // 2 x 4096
    float* s_sem  = smx + 8192;     // 21*128
    float* s_bias = smx + 10880;    // 256
    int t = threadIdx.x;
    int gp = blockIdx.x*128 + t;
    int b = gp >> 14, p = gp & (NPIX-1);

    for (int i=t;i<4096;i+=128){
        s_w[i]      = g_wcatT[i];
        s_w[4096+i] = g_inwT[i];
    }
    if (t<64){ s_bias[t]=g_bcat[t]; s_bias[64+t]=inb[t]; s_bias[128+t]=bk[t]; s_bias[192+t]=bv[t]; }
    int sbase = b*21*NPIX + p;
    #pragma unroll
    for (int kk=0;kk<21;kk++){ float sv=sem[sbase+kk*NPIX]; s_sem[kk*128+t]=sv>0.f?sv:0.f; }

    u64 xp[32];
    int xbase = b*64*NPIX + p;
    #pragma unroll
    for (int c=0;c<64;c+=2) xp[c>>1]=pack2(x[xbase+c*NPIX], x[xbase+(c+1)*NPIX]);
    __syncthreads();

    // all_feat
    u64 ap[32];
    #pragma unroll 2
    for (int j=0;j<64;j+=2){
        float d0 = dot64p(s_w + j*64, xp);
        float d1 = dot64p(s_w + (j+1)*64, xp);
        int cls0 = (j   < 4) ? 0 : ((j-4)/3 + 1);
        int cls1 = (j+1 < 4) ? 0 : ((j-3)/3 + 1);
        float f0 = s_sem[cls0*128+t]*d0 + s_bias[j];
        float f1 = s_sem[cls1*128+t]*d1 + s_bias[j+1];
        ap[j>>1] = pack2(f0, f1);
    }
    // y = all_feat @ in_w + in_b
    u64 yp[32];
    #pragma unroll 2
    for (int o=0;o<64;o+=2){
        float d0 = dot64p(s_w + 4096 + o*64, ap) + s_bias[64+o];
        float d1 = dot64p(s_w + 4096 + (o+1)*64, ap) + s_bias[65+o];
        yp[o>>1] = pack2(d0, d1);
    }
    __syncthreads();
    for (int i=t;i<4096;i+=128){
        s_w[i]      = g_wkT[i];
        s_w[4096+i] = g_wvT[i];
    }
    __syncthreads();
    #pragma unroll 2
    for (int o=0;o<64;o++) g_k[o*BN+gp] = dot64p(s_w + o*64, yp) + s_bias[128+o];
    #pragma unroll 2
    for (int o=0;o<64;o++) g_v[o*BN+gp] = dot64p(s_w + 4096 + o*64, yp) + s_bias[192+o];
}

// ------------ k2: LN-MLP -> xm, q  (128 thr, 3 CTA/SM, u staged in global) ---
// dyn smem floats: wbuf 8192 | s_p 896  => 36352 B
__global__ void __launch_bounds__(128,3)
k2(const float* __restrict__ x,
   const float* __restrict__ b1, const float* __restrict__ gm1, const float* __restrict__ be1,
   const float* __restrict__ b2, const float* __restrict__ gm2, const float* __restrict__ be2,
   const float* __restrict__ w3, const float* __restrict__ b3, const float* __restrict__ bq)
{
    extern __shared__ float smx[];
    float* wbuf = smx;            // 8192
    float* s_p  = smx + 8192;     // 896
    int t = threadIdx.x;
    int gp = blockIdx.x*128 + t;
    int b = gp >> 14, p = gp & (NPIX-1);
    for (int i=t;i<128;i+=128){
        s_p[i]=b1[i]; s_p[128+i]=gm1[i]; s_p[256+i]=be1[i];
        s_p[384+i]=b2[i]; s_p[512+i]=gm2[i]; s_p[640+i]=be2[i];
    }
    if (t<64){ s_p[768+t]=b3[t]; s_p[832+t]=bq[t]; }
    for (int i=t;i<8192;i+=128) wbuf[i]=g_w1T[i];

    u64 xp[32];
    int xbase = b*64*NPIX + p;
    #pragma unroll
    for (int c=0;c<64;c+=2) xp[c>>1]=pack2(x[xbase+c*NPIX], x[xbase+(c+1)*NPIX]);
    __syncthreads();

    // layer 1: u = x@w1 + b1  -> g_u, stats in regs
    u64 sp=0ull, s2p=0ull;
    #pragma unroll 2
    for (int o=0;o<128;o+=2){
        float u0 = dot64p(wbuf + o*64, xp) + s_p[o];
        float u1 = dot64p(wbuf + (o+1)*64, xp) + s_p[o+1];
        g_u[o*BN+gp] = u0;  g_u[(o+1)*BN+gp] = u1;
        u64 up = pack2(u0,u1);
        sp = add2_(sp, up);
        s2p = fma2_(up, up, s2p);
    }
    float s = hadd2(sp), s2 = hadd2(s2p);
    float m = s*(1.f/128.f), var = s2*(1.f/128.f)-m*m, rinv = rsqrtf(var+1e-5f);

    u64 hp[64];
    #pragma unroll 4
    for (int i=0;i<64;i++){
        float u0 = g_u[(2*i)*BN+gp], u1 = g_u[(2*i+1)*BN+gp];
        float v0=(u0-m)*rinv*s_p[128+2*i]+s_p[256+2*i];
        float v1=(u1-m)*rinv*s_p[128+2*i+1]+s_p[256+2*i+1];
        v0 = v0>0.f?v0:0.01f*v0;
        v1 = v1>0.f?v1:0.01f*v1;
        hp[i]=pack2(v0,v1);
    }

    // layer 2: two weight halves
    sp=0ull; s2p=0ull;
    __syncthreads();
    for (int i=t;i<8192;i+=128) wbuf[i]=g_w2T[i];
    __syncthreads();
    #pragma unroll 2
    for (int o=0;o<64;o+=2){
        float u0 = dot128p(wbuf + o*128, hp) + s_p[384+o];
        float u1 = dot128p(wbuf + (o+1)*128, hp) + s_p[384+o+1];
        g_u[o*BN+gp]=u0; g_u[(o+1)*BN+gp]=u1;
        u64 up = pack2(u0,u1);
        sp = add2_(sp, up); s2p = fma2_(up, up, s2p);
    }
    __syncthreads();
    for (int i=t;i<8192;i+=128) wbuf[i]=g_w2T[8192+i];
    __syncthreads();
    #pragma unroll 2
    for (int o=64;o<128;o+=2){
        float u0 = dot128p(wbuf + (o-64)*128, hp) + s_p[384+o];
        float u1 = dot128p(wbuf + (o-63)*128, hp) + s_p[384+o+1];
        g_u[o*BN+gp]=u0; g_u[(o+1)*BN+gp]=u1;
        u64 up = pack2(u0,u1);
        sp = add2_(sp, up); s2p = fma2_(up, up, s2p);
    }
    s = hadd2(sp); s2 = hadd2(s2p);
    m = s*(1.f/128.f); var = s2*(1.f/128.f)-m*m; rinv = rsqrtf(var+1e-5f);

    // layer 3: xm = lrelu(LN(u2)) @ w3 + b3
    __syncthreads();
    for (int i=t;i<8192;i+=128) wbuf[i]=w3[i];
    __syncthreads();
    u64 xmp[32];
    #pragma unroll
    for (int c=0;c<64;c+=2) xmp[c>>1] = pack2(s_p[768+c], s_p[768+c+1]);
    #pragma unroll 2
    for (int i=0;i<128;i+=2){
        float u0 = g_u[i*BN+gp], u1 = g_u[(i+1)*BN+gp];
        float v0=(u0-m)*rinv*s_p[512+i]+s_p[640+i];
        float v1=(u1-m)*rinv*s_p[512+i+1]+s_p[640+i+1];
        v0 = v0>0.f?v0:0.01f*v0;
        v1 = v1>0.f?v1:0.01f*v1;
        u64 vv0=pack2(v0,v0), vv1=pack2(v1,v1);
        const ulonglong2* w0=(const ulonglong2*)(wbuf + i*64);
        const ulonglong2* w1p=(const ulonglong2*)(wbuf + (i+1)*64);
        #pragma unroll
        for (int c2=0;c2<16;c2++){
            ulonglong2 wa=w0[c2], wb=w1p[c2];
            xmp[2*c2+0]=fma2_(vv0, wa.x, xmp[2*c2+0]);
            xmp[2*c2+1]=fma2_(vv0, wa.y, xmp[2*c2+1]);
            xmp[2*c2+0]=fma2_(vv1, wb.x, xmp[2*c2+0]);
            xmp[2*c2+1]=fma2_(vv1, wb.y, xmp[2*c2+1]);
        }
    }
    #pragma unroll
    for (int c=0;c<64;c+=2){
        float v0,v1; unpack2(xmp[c>>1], v0, v1);
        g_xm[c*BN+gp]=v0; g_xm[(c+1)*BN+gp]=v1;
    }
    // q = xm @ wq + bq
    __syncthreads();
    for (int i=t;i<4096;i+=128) wbuf[i]=g_wqT[i];
    __syncthreads();
    #pragma unroll 2
    for (int j=0;j<64;j++)
        g_q[j*BN+gp] = dot64p(wbuf + j*64, xmp) + s_p[832+j];
}

// ------------ k3: Gram + norm partials per 128-pixel chunk -------------------
#define CHUNK 128
#define TP 129
__global__ void __launch_bounds__(256,2) k3()
{
    extern __shared__ float smx[];
    float* qs  = smx;             // 64*129
    float* ks  = smx + 64*TP;     // 64*129
    float* red = smx + 128*TP;    // 4096
    int t = threadIdx.x;
    int chunk = blockIdx.x, b = blockIdx.y;
    int pbase = b*NPIX + chunk*CHUNK;
    for (int i=t; i<64*CHUNK; i+=256){
        int ch=i>>7, pp=i&(CHUNK-1);
        qs[ch*TP+pp]=g_q[ch*BN+pbase+pp];
        ks[ch*TP+pp]=g_k[ch*BN+pbase+pp];
    }
    __syncthreads();
    int sub=t>>6, combo=t&63;
    int h=combo>>4, d4=(combo>>2)&3, e4=combo&3;
    const float* qsb=qs+(h*16+d4*4)*TP;
    const float* ksb=ks+(h*16+e4*4)*TP;
    float acc[4][4];
    #pragma unroll
    for (int i=0;i<4;i++)
        #pragma unroll
        for (int j=0;j<4;j++) acc[i][j]=0.f;
    for (int pp=sub*32; pp<sub*32+32; pp++){
        float q0=qsb[pp],q1=qsb[TP+pp],q2=qsb[2*TP+pp],q3=qsb[3*TP+pp];
        float k0=ksb[pp],k1v=ksb[TP+pp],k2v=ksb[2*TP+pp],k3v=ksb[3*TP+pp];
        acc[0][0]=fmaf(q0,k0,acc[0][0]); acc[0][1]=fmaf(q0,k1v,acc[0][1]); acc[0][2]=fmaf(q0,k2v,acc[0][2]); acc[0][3]=fmaf(q0,k3v,acc[0][3]);
        acc[1][0]=fmaf(q1,k0,acc[1][0]); acc[1][1]=fmaf(q1,k1v,acc[1][1]); acc[1][2]=fmaf(q1,k2v,acc[1][2]); acc[1][3]=fmaf(q1,k3v,acc[1][3]);
        acc[2][0]=fmaf(q2,k0,acc[2][0]); acc[2][1]=fmaf(q2,k1v,acc[2][1]); acc[2][2]=fmaf(q2,k2v,acc[2][2]); acc[2][3]=fmaf(q2,k3v,acc[2][3]);
        acc[3][0]=fmaf(q3,k0,acc[3][0]); acc[3][1]=fmaf(q3,k1v,acc[3][1]); acc[3][2]=fmaf(q3,k2v,acc[3][2]); acc[3][3]=fmaf(q3,k3v,acc[3][3]);
    }
    #pragma unroll
    for (int i=0;i<4;i++)
        #pragma unroll
        for (int j=0;j<4;j++)
            red[sub*1024 + (h*16+d4*4+i)*16 + (e4*4+j)] = acc[i][j];
    if (t < 64){
        const float* qr=qs+t*TP;
        float a0=0,a1=0,a2=0,a3=0;
        for (int pp=0;pp<CHUNK;pp+=4){
            a0=fmaf(qr[pp+0],qr[pp+0],a0); a1=fmaf(qr[pp+1],qr[pp+1],a1);
            a2=fmaf(qr[pp+2],qr[pp+2],a2); a3=fmaf(qr[pp+3],qr[pp+3],a3);
        }
        g_sqp[(b*128+chunk)*64+t]=(a0+a1)+(a2+a3);
    } else if (t < 128){
        int ch=t-64;
        const float* kr=ks+ch*TP;
        float a0=0,a1=0,a2=0,a3=0;
        for (int pp=0;pp<CHUNK;pp+=4){
            a0=fmaf(kr[pp+0],kr[pp+0],a0); a1=fmaf(kr[pp+1],kr[pp+1],a1);
            a2=fmaf(kr[pp+2],kr[pp+2],a2); a3=fmaf(kr[pp+3],kr[pp+3],a3);
        }
        g_skp[(b*128+chunk)*64+ch]=(a0+a1)+(a2+a3);
    }
    __syncthreads();
    float* gout = g_Gpart + (b*128+chunk)*1024;
    for (int idx=t; idx<1024; idx+=256)
        gout[idx] = (red[idx]+red[1024+idx]) + (red[2048+idx]+red[3072+idx]);
}

// ------------ k4: reduce + normalize + softmax -> A --------------------------
__global__ void k4(const float* __restrict__ rescale)
{
    __shared__ float sG[1024];
    __shared__ float snq[64], snk[64];
    int b=blockIdx.x, t=threadIdx.x;
    {
        float a0=0.f,a1=0.f,a2=0.f,a3=0.f;
        for (int c=0;c<128;c++){
            const float4 v = ((const float4*)(g_Gpart+(b*128+c)*1024))[t];
            a0+=v.x; a1+=v.y; a2+=v.z; a3+=v.w;
        }
        sG[t*4+0]=a0; sG[t*4+1]=a1; sG[t*4+2]=a2; sG[t*4+3]=a3;
    }
    if (t<64){
        float aq=0.f, ak=0.f;
        for (int c=0;c<128;c++){ aq+=g_sqp[(b*128+c)*64+t]; ak+=g_skp[(b*128+c)*64+t]; }
        snq[t]=sqrtf(aq)+1e-8f; snk[t]=sqrtf(ak)+1e-8f;
    }
    __syncthreads();
    if (t<64){
        int h=t>>4;
        float r=rescale[h], nq=snq[t];
        float ev[16]; float mx=-1e30f;
        #pragma unroll
        for (int e=0;e<16;e++){ ev[e]=sG[t*16+e]/(nq*snk[h*16+e])*r; mx=fmaxf(mx,ev[e]); }
        float ss=0.f;
        #pragma unroll
        for (int e=0;e<16;e++){ ev[e]=expf(ev[e]-mx); ss+=ev[e]; }
        float inv=1.f/ss;
        #pragma unroll
        for (int e=0;e<16;e++) g_A[b*1024 + t*16+e]=ev[e]*inv;
    }
}

// ------------ k4b: Weff[b] = blockdiag(A)^T folded into wo -------------------
__global__ void k4b(const float* __restrict__ wo)
{
    __shared__ float sA[1024];
    __shared__ float swo[4096];
    int b=blockIdx.x, t=threadIdx.x;
    for (int i=t;i<1024;i+=256) sA[i]=g_A[b*1024+i];
    for (int i=t;i<4096;i+=256) swo[i]=wo[i];
    __syncthreads();
    for (int idx=t; idx<4096; idx+=256){
        int cp=idx>>6, e=idx&63, h=e>>4, e15=e&15;
        float acc=0.f;
        #pragma unroll
        for (int d=0;d<16;d++)
            acc = fmaf(sA[h*256 + d*16 + e15], swo[(h*16+d)*64 + cp], acc);
        g_weffT[b*4096 + cp*64 + e] = acc;
    }
}

// ------------ k5: out = v @ WeffT + bo + xm ----------------------------------
__global__ void __launch_bounds__(128,4)
k5(const float* __restrict__ bo, float* __restrict__ out)
{
    __shared__ __align__(16) float sw[4096];
    __shared__ float sbo[64];
    int t=threadIdx.x;
    int gp=blockIdx.x*128+t;
    int b=gp>>14, p=gp&(NPIX-1);
    for (int i=t;i<4096;i+=128) sw[i]=g_weffT[b*4096+i];
    if (t<64) sbo[t]=bo[t];
    u64 vp[32];
    #pragma unroll
    for (int e=0;e<64;e+=2) vp[e>>1]=pack2(g_v[e*BN+gp], g_v[(e+1)*BN+gp]);
    __syncthreads();
    #pragma unroll 2
    for (int cp=0;cp<64;cp++){
        float d = dot64p(sw+cp*64, vp) + sbo[cp] + g_xm[cp*BN+gp];
        out[(size_t)(b*64+cp)*NPIX + p] = d;
    }
}

// ------------ launch ----------------------------------------------------------
extern "C" void kernel_launch(void* const* d_in, const int* in_sizes, int n_in,
                              void* d_out, int out_size)
{
    const float* x   =(const float*)d_in[0];
    const float* sem =(const float*)d_in[1];
    const float* wa  =(const float*)d_in[2];
    const float* ba  =(const float*)d_in[3];
    const float* wb  =(const float*)d_in[4];
    const float* bb  =(const float*)d_in[5];
    const float* inw =(const float*)d_in[6];
    const float* inb =(const float*)d_in[7];
    const float* w1  =(const float*)d_in[8];
    const float* b1  =(const float*)d_in[9];
    const float* gm1 =(const float*)d_in[10];
    const float* be1 =(const float*)d_in[11];
    const float* w2  =(const float*)d_in[12];
    const float* b2  =(const float*)d_in[13];
    const float* gm2 =(const float*)d_in[14];
    const float* be2 =(const float*)d_in[15];
    const float* w3  =(const float*)d_in[16];
    const float* b3  =(const float*)d_in[17];
    const float* wq  =(const float*)d_in[18];
    const float* bq  =(const float*)d_in[19];
    const float* wk  =(const float*)d_in[20];
    const float* bk  =(const float*)d_in[21];
    const float* wv  =(const float*)d_in[22];
    const float* bv  =(const float*)d_in[23];
    const float* wo  =(const float*)d_in[24];
    const float* bo  =(const float*)d_in[25];
    const float* rescale=(const float*)d_in[26];
    float* out=(float*)d_out;

    cudaFuncSetAttribute(k1, cudaFuncAttributeMaxDynamicSharedMemorySize, 11136*4);
    cudaFuncSetAttribute(k2, cudaFuncAttributeMaxDynamicSharedMemorySize, 9088*4);
    cudaFuncSetAttribute(k3, cudaFuncAttributeMaxDynamicSharedMemorySize, (128*TP+4096)*4);

    kprep<<<64,256>>>(wa,ba,wb,bb,inw,wk,wv,wq,w1,w2);
    k1<<<512,128,11136*4>>>(x,sem,inb,bk,bv);
    k2<<<512,128,9088*4>>>(x,b1,gm1,be1,b2,gm2,be2,w3,b3,bq);
    k3<<<dim3(128,4),256,(128*TP+4096)*4>>>();
    k4<<<4,256>>>(rescale);
    k4b<<<4,256>>>(wo);
    k5<<<512,128>>>(bo,out);
}

// round 7
// speedup vs baseline: 1.0062x; 1.0062x over previous
#include <cuda_runtime.h>
#include <math.h>

#define NPIX 16384
#define BN   65536   // 4 * 16384

typedef unsigned long long u64;

// ------------ scratch ------------------------------------------------------
__device__ float g_k[64*BN];
__device__ float g_v[64*BN];
__device__ float g_q[64*BN];
__device__ float g_xm[64*BN];
__device__ float g_u[128*BN];          // LN staging (L2-resident)
__device__ float g_Gpart[4*128*1024];
__device__ float g_sqp[4*128*64];
__device__ float g_skp[4*128*64];
__device__ float g_A[4096];
__device__ float g_weffT[4*4096];
__device__ float g_wcatT[4096];
__device__ float g_inwT[4096];
__device__ float g_wkT[4096];
__device__ float g_wvT[4096];
__device__ float g_wqT[4096];
__device__ float g_w1T[8192];
__device__ float g_w2T[16384];
__device__ float g_bcat[64];

// ------------ f32x2 helpers --------------------------------------------------
__device__ __forceinline__ u64 pack2(float lo, float hi){
    u64 r; asm("mov.b64 %0, {%1,%2};" : "=l"(r) : "f"(lo), "f"(hi)); return r;
}
__device__ __forceinline__ void unpack2(u64 a, float& lo, float& hi){
    asm("mov.b64 {%0,%1}, %2;" : "=f"(lo), "=f"(hi) : "l"(a));
}
__device__ __forceinline__ u64 fma2_(u64 a, u64 b, u64 c){
    u64 d; asm("fma.rn.f32x2 %0, %1, %2, %3;" : "=l"(d) : "l"(a), "l"(b), "l"(c)); return d;
}
__device__ __forceinline__ u64 add2_(u64 a, u64 b){
    u64 d; asm("add.rn.f32x2 %0, %1, %2;" : "=l"(d) : "l"(a), "l"(b)); return d;
}
__device__ __forceinline__ float hadd2(u64 a){
    float lo, hi; unpack2(a, lo, hi); return lo + hi;
}

__device__ __forceinline__ float dot64p(const float* w, const u64* xp){
    const ulonglong2* w2 = (const ulonglong2*)w;
    u64 a0=0ull,a1=0ull,a2=0ull,a3=0ull;
    #pragma unroll
    for (int i=0;i<8;i++){
        ulonglong2 wa=w2[2*i], wb=w2[2*i+1];
        a0=fma2_(xp[4*i+0], wa.x, a0);
        a1=fma2_(xp[4*i+1], wa.y, a1);
        a2=fma2_(xp[4*i+2], wb.x, a2);
        a3=fma2_(xp[4*i+3], wb.y, a3);
    }
    return hadd2(add2_(add2_(a0,a1),add2_(a2,a3)));
}
__device__ __forceinline__ float dot128p(const float* w, const u64* xp){
    const ulonglong2* w2 = (const ulonglong2*)w;
    u64 a0=0ull,a1=0ull,a2=0ull,a3=0ull;
    #pragma unroll
    for (int i=0;i<16;i++){
        ulonglong2 wa=w2[2*i], wb=w2[2*i+1];
        a0=fma2_(xp[4*i+0], wa.x, a0);
        a1=fma2_(xp[4*i+1], wa.y, a1);
        a2=fma2_(xp[4*i+2], wb.x, a2);
        a3=fma2_(xp[4*i+3], wb.y, a3);
    }
    return hadd2(add2_(add2_(a0,a1),add2_(a2,a3)));
}

// ------------ kprep ----------------------------------------------------------
__global__ void kprep(const float* wa, const float* ba, const float* wb, const float* bb,
                      const float* inw, const float* wk, const float* wv, const float* wq,
                      const float* w1, const float* w2)
{
    int t = blockIdx.x*256 + threadIdx.x;     // 0..16383
    if (t < 4096) {
        int j = t>>6, c = t&63;
        float w;
        if (j < 4) w = wa[c*4 + j];
        else { int u=j-4; int kk=u/3; int d=u-kk*3; w = wb[kk*192 + c*3 + d]; }
        g_wcatT[t] = w;
        g_inwT[t]  = inw[c*64 + j];
        g_wkT[t]   = wk[c*64 + j];
        g_wvT[t]   = wv[c*64 + j];
        g_wqT[t]   = wq[c*64 + j];
    }
    if (t < 8192)  { int o=t>>6, c=t&63;  g_w1T[t] = w1[c*128 + o]; }
    if (t < 16384) { int o=t>>7, i=t&127; g_w2T[t] = w2[i*128 + o]; }
    if (t < 64) g_bcat[t] = (t < 4) ? ba[t] : bb[t-4];
}

// ------------ k1: feat path -> y -> k, v  (128 thr, 3 CTA/SM) ----------------
// dyn smem floats: s_w 8192 | s_sem 2688 | s_bias 256  => 44544 B
__global__ void __launch_bounds__(128,3)
k1(const float* __restrict__ x, const float* __restrict__ sem,
   const float* __restrict__ inb, const float* __restrict__ bk, const float* __restrict__ bv)
{
    extern __shared__ float smx[];
    float* s_w    = smx;            // 2 x 4096
    float* s_sem  = smx + 8192;     // 21*128
    float* s_bias = smx + 10880;    // 256
    int t = threadIdx.x;
    int gp = blockIdx.x*128 + t;
    int b = gp >> 14, p = gp & (NPIX-1);

    for (int i=t;i<4096;i+=128){
        s_w[i]      = g_wcatT[i];
        s_w[4096+i] = g_inwT[i];
    }
    if (t<64){ s_bias[t]=g_bcat[t]; s_bias[64+t]=inb[t]; s_bias[128+t]=bk[t]; s_bias[192+t]=bv[t]; }
    int sbase = b*21*NPIX + p;
    #pragma unroll
    for (int kk=0;kk<21;kk++){ float sv=sem[sbase+kk*NPIX]; s_sem[kk*128+t]=sv>0.f?sv:0.f; }

    u64 xp[32];
    int xbase = b*64*NPIX + p;
    #pragma unroll
    for (int c=0;c<64;c+=2) xp[c>>1]=pack2(x[xbase+c*NPIX], x[xbase+(c+1)*NPIX]);
    __syncthreads();

    // all_feat
    u64 ap[32];
    #pragma unroll 2
    for (int j=0;j<64;j+=2){
        float d0 = dot64p(s_w + j*64, xp);
        float d1 = dot64p(s_w + (j+1)*64, xp);
        int cls0 = (j   < 4) ? 0 : ((j-4)/3 + 1);
        int cls1 = (j+1 < 4) ? 0 : ((j-3)/3 + 1);
        float f0 = s_sem[cls0*128+t]*d0 + s_bias[j];
        float f1 = s_sem[cls1*128+t]*d1 + s_bias[j+1];
        ap[j>>1] = pack2(f0, f1);
    }
    // y = all_feat @ in_w + in_b
    u64 yp[32];
    #pragma unroll 2
    for (int o=0;o<64;o+=2){
        float d0 = dot64p(s_w + 4096 + o*64, ap) + s_bias[64+o];
        float d1 = dot64p(s_w + 4096 + (o+1)*64, ap) + s_bias[65+o];
        yp[o>>1] = pack2(d0, d1);
    }
    __syncthreads();
    for (int i=t;i<4096;i+=128){
        s_w[i]      = g_wkT[i];
        s_w[4096+i] = g_wvT[i];
    }
    __syncthreads();
    #pragma unroll 2
    for (int o=0;o<64;o++) g_k[o*BN+gp] = dot64p(s_w + o*64, yp) + s_bias[128+o];
    #pragma unroll 2
    for (int o=0;o<64;o++) g_v[o*BN+gp] = dot64p(s_w + 4096 + o*64, yp) + s_bias[192+o];
}

// ------------ k2: LN-MLP -> xm, q  (128 thr, 3 CTA/SM, u staged in global) ---
// dyn smem floats: wbuf 8192 | s_p 896  => 36352 B
__global__ void __launch_bounds__(128,3)
k2(const float* __restrict__ x,
   const float* __restrict__ b1, const float* __restrict__ gm1, const float* __restrict__ be1,
   const float* __restrict__ b2, const float* __restrict__ gm2, const float* __restrict__ be2,
   const float* __restrict__ w3, const float* __restrict__ b3, const float* __restrict__ bq)
{
    extern __shared__ float smx[];
    float* wbuf = smx;            // 8192
    float* s_p  = smx + 8192;     // 896
    int t = threadIdx.x;
    int gp = blockIdx.x*128 + t;
    int b = gp >> 14, p = gp & (NPIX-1);
    for (int i=t;i<128;i+=128){
        s_p[i]=b1[i]; s_p[128+i]=gm1[i]; s_p[256+i]=be1[i];
        s_p[384+i]=b2[i]; s_p[512+i]=gm2[i]; s_p[640+i]=be2[i];
    }
    if (t<64){ s_p[768+t]=b3[t]; s_p[832+t]=bq[t]; }
    for (int i=t;i<8192;i+=128) wbuf[i]=g_w1T[i];

    u64 xp[32];
    int xbase = b*64*NPIX + p;
    #pragma unroll
    for (int c=0;c<64;c+=2) xp[c>>1]=pack2(x[xbase+c*NPIX], x[xbase+(c+1)*NPIX]);
    __syncthreads();

    // layer 1: u = x@w1 + b1  -> g_u, stats in regs
    u64 sp=0ull, s2p=0ull;
    #pragma unroll 2
    for (int o=0;o<128;o+=2){
        float u0 = dot64p(wbuf + o*64, xp) + s_p[o];
        float u1 = dot64p(wbuf + (o+1)*64, xp) + s_p[o+1];
        g_u[o*BN+gp] = u0;  g_u[(o+1)*BN+gp] = u1;
        u64 up = pack2(u0,u1);
        sp = add2_(sp, up);
        s2p = fma2_(up, up, s2p);
    }
    float s = hadd2(sp), s2 = hadd2(s2p);
    float m = s*(1.f/128.f), var = s2*(1.f/128.f)-m*m, rinv = rsqrtf(var+1e-5f);

    u64 hp[64];
    #pragma unroll 4
    for (int i=0;i<64;i++){
        float u0 = g_u[(2*i)*BN+gp], u1 = g_u[(2*i+1)*BN+gp];
        float v0=(u0-m)*rinv*s_p[128+2*i]+s_p[256+2*i];
        float v1=(u1-m)*rinv*s_p[128+2*i+1]+s_p[256+2*i+1];
        v0 = v0>0.f?v0:0.01f*v0;
        v1 = v1>0.f?v1:0.01f*v1;
        hp[i]=pack2(v0,v1);
    }

    // layer 2: two weight halves
    sp=0ull; s2p=0ull;
    __syncthreads();
    for (int i=t;i<8192;i+=128) wbuf[i]=g_w2T[i];
    __syncthreads();
    #pragma unroll 2
    for (int o=0;o<64;o+=2){
        float u0 = dot128p(wbuf + o*128, hp) + s_p[384+o];
        float u1 = dot128p(wbuf + (o+1)*128, hp) + s_p[384+o+1];
        g_u[o*BN+gp]=u0; g_u[(o+1)*BN+gp]=u1;
        u64 up = pack2(u0,u1);
        sp = add2_(sp, up); s2p = fma2_(up, up, s2p);
    }
    __syncthreads();
    for (int i=t;i<8192;i+=128) wbuf[i]=g_w2T[8192+i];
    __syncthreads();
    #pragma unroll 2
    for (int o=64;o<128;o+=2){
        float u0 = dot128p(wbuf + (o-64)*128, hp) + s_p[384+o];
        float u1 = dot128p(wbuf + (o-63)*128, hp) + s_p[384+o+1];
        g_u[o*BN+gp]=u0; g_u[(o+1)*BN+gp]=u1;
        u64 up = pack2(u0,u1);
        sp = add2_(sp, up); s2p = fma2_(up, up, s2p);
    }
    s = hadd2(sp); s2 = hadd2(s2p);
    m = s*(1.f/128.f); var = s2*(1.f/128.f)-m*m; rinv = rsqrtf(var+1e-5f);

    // layer 3: xm = lrelu(LN(u2)) @ w3 + b3
    __syncthreads();
    for (int i=t;i<8192;i+=128) wbuf[i]=w3[i];
    __syncthreads();
    u64 xmp[32];
    #pragma unroll
    for (int c=0;c<64;c+=2) xmp[c>>1] = pack2(s_p[768+c], s_p[768+c+1]);
    #pragma unroll 2
    for (int i=0;i<128;i+=2){
        float u0 = g_u[i*BN+gp], u1 = g_u[(i+1)*BN+gp];
        float v0=(u0-m)*rinv*s_p[512+i]+s_p[640+i];
        float v1=(u1-m)*rinv*s_p[512+i+1]+s_p[640+i+1];
        v0 = v0>0.f?v0:0.01f*v0;
        v1 = v1>0.f?v1:0.01f*v1;
        u64 vv0=pack2(v0,v0), vv1=pack2(v1,v1);
        const ulonglong2* w0=(const ulonglong2*)(wbuf + i*64);
        const ulonglong2* w1p=(const ulonglong2*)(wbuf + (i+1)*64);
        #pragma unroll
        for (int c2=0;c2<16;c2++){
            ulonglong2 wa=w0[c2], wb=w1p[c2];
            xmp[2*c2+0]=fma2_(vv0, wa.x, xmp[2*c2+0]);
            xmp[2*c2+1]=fma2_(vv0, wa.y, xmp[2*c2+1]);
            xmp[2*c2+0]=fma2_(vv1, wb.x, xmp[2*c2+0]);
            xmp[2*c2+1]=fma2_(vv1, wb.y, xmp[2*c2+1]);
        }
    }
    #pragma unroll
    for (int c=0;c<64;c+=2){
        float v0,v1; unpack2(xmp[c>>1], v0, v1);
        g_xm[c*BN+gp]=v0; g_xm[(c+1)*BN+gp]=v1;
    }
    // q = xm @ wq + bq
    __syncthreads();
    for (int i=t;i<4096;i+=128) wbuf[i]=g_wqT[i];
    __syncthreads();
    #pragma unroll 2
    for (int j=0;j<64;j++)
        g_q[j*BN+gp] = dot64p(wbuf + j*64, xmp) + s_p[832+j];
}

// ------------ k3: Gram + norm partials per 128-pixel chunk -------------------
#define CHUNK 128
#define TP 129
__global__ void __launch_bounds__(256,2) k3()
{
    extern __shared__ float smx[];
    float* qs  = smx;             // 64*129
    float* ks  = smx + 64*TP;     // 64*129
    float* red = smx + 128*TP;    // 4096
    int t = threadIdx.x;
    int chunk = blockIdx.x, b = blockIdx.y;
    int pbase = b*NPIX + chunk*CHUNK;
    for (int i=t; i<64*CHUNK; i+=256){
        int ch=i>>7, pp=i&(CHUNK-1);
        qs[ch*TP+pp]=g_q[ch*BN+pbase+pp];
        ks[ch*TP+pp]=g_k[ch*BN+pbase+pp];
    }
    __syncthreads();
    int sub=t>>6, combo=t&63;
    int h=combo>>4, d4=(combo>>2)&3, e4=combo&3;
    const float* qsb=qs+(h*16+d4*4)*TP;
    const float* ksb=ks+(h*16+e4*4)*TP;
    float acc[4][4];
    #pragma unroll
    for (int i=0;i<4;i++)
        #pragma unroll
        for (int j=0;j<4;j++) acc[i][j]=0.f;
    for (int pp=sub*32; pp<sub*32+32; pp++){
        float q0=qsb[pp],q1=qsb[TP+pp],q2=qsb[2*TP+pp],q3=qsb[3*TP+pp];
        float k0=ksb[pp],k1v=ksb[TP+pp],k2v=ksb[2*TP+pp],k3v=ksb[3*TP+pp];
        acc[0][0]=fmaf(q0,k0,acc[0][0]); acc[0][1]=fmaf(q0,k1v,acc[0][1]); acc[0][2]=fmaf(q0,k2v,acc[0][2]); acc[0][3]=fmaf(q0,k3v,acc[0][3]);
        acc[1][0]=fmaf(q1,k0,acc[1][0]); acc[1][1]=fmaf(q1,k1v,acc[1][1]); acc[1][2]=fmaf(q1,k2v,acc[1][2]); acc[1][3]=fmaf(q1,k3v,acc[1][3]);
        acc[2][0]=fmaf(q2,k0,acc[2][0]); acc[2][1]=fmaf(q2,k1v,acc[2][1]); acc[2][2]=fmaf(q2,k2v,acc[2][2]); acc[2][3]=fmaf(q2,k3v,acc[2][3]);
        acc[3][0]=fmaf(q3,k0,acc[3][0]); acc[3][1]=fmaf(q3,k1v,acc[3][1]); acc[3][2]=fmaf(q3,k2v,acc[3][2]); acc[3][3]=fmaf(q3,k3v,acc[3][3]);
    }
    #pragma unroll
    for (int i=0;i<4;i++)
        #pragma unroll
        for (int j=0;j<4;j++)
            red[sub*1024 + (h*16+d4*4+i)*16 + (e4*4+j)] = acc[i][j];
    if (t < 64){
        const float* qr=qs+t*TP;
        float a0=0,a1=0,a2=0,a3=0;
        for (int pp=0;pp<CHUNK;pp+=4){
            a0=fmaf(qr[pp+0],qr[pp+0],a0); a1=fmaf(qr[pp+1],qr[pp+1],a1);
            a2=fmaf(qr[pp+2],qr[pp+2],a2); a3=fmaf(qr[pp+3],qr[pp+3],a3);
        }
        g_sqp[(b*128+chunk)*64+t]=(a0+a1)+(a2+a3);
    } else if (t < 128){
        int ch=t-64;
        const float* kr=ks+ch*TP;
        float a0=0,a1=0,a2=0,a3=0;
        for (int pp=0;pp<CHUNK;pp+=4){
            a0=fmaf(kr[pp+0],kr[pp+0],a0); a1=fmaf(kr[pp+1],kr[pp+1],a1);
            a2=fmaf(kr[pp+2],kr[pp+2],a2); a3=fmaf(kr[pp+3],kr[pp+3],a3);
        }
        g_skp[(b*128+chunk)*64+ch]=(a0+a1)+(a2+a3);
    }
    __syncthreads();
    float* gout = g_Gpart + (b*128+chunk)*1024;
    for (int idx=t; idx<1024; idx+=256)
        gout[idx] = (red[idx]+red[1024+idx]) + (red[2048+idx]+red[3072+idx]);
}

// ------------ k4: reduce + normalize + softmax -> A --------------------------
__global__ void k4(const float* __restrict__ rescale)
{
    __shared__ float sG[1024];
    __shared__ float snq[64], snk[64];
    int b=blockIdx.x, t=threadIdx.x;
    {
        float a0=0.f,a1=0.f,a2=0.f,a3=0.f;
        for (int c=0;c<128;c++){
            const float4 v = ((const float4*)(g_Gpart+(b*128+c)*1024))[t];
            a0+=v.x; a1+=v.y; a2+=v.z; a3+=v.w;
        }
        sG[t*4+0]=a0; sG[t*4+1]=a1; sG[t*4+2]=a2; sG[t*4+3]=a3;
    }
    if (t<64){
        float aq=0.f, ak=0.f;
        for (int c=0;c<128;c++){ aq+=g_sqp[(b*128+c)*64+t]; ak+=g_skp[(b*128+c)*64+t]; }
        snq[t]=sqrtf(aq)+1e-8f; snk[t]=sqrtf(ak)+1e-8f;
    }
    __syncthreads();
    if (t<64){
        int h=t>>4;
        float r=rescale[h], nq=snq[t];
        float ev[16]; float mx=-1e30f;
        #pragma unroll
        for (int e=0;e<16;e++){ ev[e]=sG[t*16+e]/(nq*snk[h*16+e])*r; mx=fmaxf(mx,ev[e]); }
        float ss=0.f;
        #pragma unroll
        for (int e=0;e<16;e++){ ev[e]=expf(ev[e]-mx); ss+=ev[e]; }
        float inv=1.f/ss;
        #pragma unroll
        for (int e=0;e<16;e++) g_A[b*1024 + t*16+e]=ev[e]*inv;
    }
}

// ------------ k4b: Weff[b] = blockdiag(A)^T folded into wo -------------------
__global__ void k4b(const float* __restrict__ wo)
{
    __shared__ float sA[1024];
    __shared__ float swo[4096];
    int b=blockIdx.x, t=threadIdx.x;
    for (int i=t;i<1024;i+=256) sA[i]=g_A[b*1024+i];
    for (int i=t;i<4096;i+=256) swo[i]=wo[i];
    __syncthreads();
    for (int idx=t; idx<4096; idx+=256){
        int cp=idx>>6, e=idx&63, h=e>>4, e15=e&15;
        float acc=0.f;
        #pragma unroll
        for (int d=0;d<16;d++)
            acc = fmaf(sA[h*256 + d*16 + e15], swo[(h*16+d)*64 + cp], acc);
        g_weffT[b*4096 + cp*64 + e] = acc;
    }
}

// ------------ k5: out = v @ WeffT + bo + xm ----------------------------------
__global__ void __launch_bounds__(128,4)
k5(const float* __restrict__ bo, float* __restrict__ out)
{
    __shared__ __align__(16) float sw[4096];
    __shared__ float sbo[64];
    int t=threadIdx.x;
    int gp=blockIdx.x*128+t;
    int b=gp>>14, p=gp&(NPIX-1);
    for (int i=t;i<4096;i+=128) sw[i]=g_weffT[b*4096+i];
    if (t<64) sbo[t]=bo[t];
    u64 vp[32];
    #pragma unroll
    for (int e=0;e<64;e+=2) vp[e>>1]=pack2(g_v[e*BN+gp], g_v[(e+1)*BN+gp]);
    __syncthreads();
    #pragma unroll 2
    for (int cp=0;cp<64;cp++){
        float d = dot64p(sw+cp*64, vp) + sbo[cp] + g_xm[cp*BN+gp];
        out[(size_t)(b*64+cp)*NPIX + p] = d;
    }
}

// ------------ launch ----------------------------------------------------------
extern "C" void kernel_launch(void* const* d_in, const int* in_sizes, int n_in,
                              void* d_out, int out_size)
{
    const float* x   =(const float*)d_in[0];
    const float* sem =(const float*)d_in[1];
    const float* wa  =(const float*)d_in[2];
    const float* ba  =(const float*)d_in[3];
    const float* wb  =(const float*)d_in[4];
    const float* bb  =(const float*)d_in[5];
    const float* inw =(const float*)d_in[6];
    const float* inb =(const float*)d_in[7];
    const float* w1  =(const float*)d_in[8];
    const float* b1  =(const float*)d_in[9];
    const float* gm1 =(const float*)d_in[10];
    const float* be1 =(const float*)d_in[11];
    const float* w2  =(const float*)d_in[12];
    const float* b2  =(const float*)d_in[13];
    const float* gm2 =(const float*)d_in[14];
    const float* be2 =(const float*)d_in[15];
    const float* w3  =(const float*)d_in[16];
    const float* b3  =(const float*)d_in[17];
    const float* wq  =(const float*)d_in[18];
    const float* bq  =(const float*)d_in[19];
    const float* wk  =(const float*)d_in[20];
    const float* bk  =(const float*)d_in[21];
    const float* wv  =(const float*)d_in[22];
    const float* bv  =(const float*)d_in[23];
    const float* wo  =(const float*)d_in[24];
    const float* bo  =(const float*)d_in[25];
    const float* rescale=(const float*)d_in[26];
    float* out=(float*)d_out;

    cudaFuncSetAttribute(k1, cudaFuncAttributeMaxDynamicSharedMemorySize, 11136*4);
    cudaFuncSetAttribute(k2, cudaFuncAttributeMaxDynamicSharedMemorySize, 9088*4);
    cudaFuncSetAttribute(k3, cudaFuncAttributeMaxDynamicSharedMemorySize, (128*TP+4096)*4);

    kprep<<<64,256>>>(wa,ba,wb,bb,inw,wk,wv,wq,w1,w2);
    k1<<<512,128,11136*4>>>(x,sem,inb,bk,bv);
    k2<<<512,128,9088*4>>>(x,b1,gm1,be1,b2,gm2,be2,w3,b3,bq);
    k3<<<dim3(128,4),256,(128*TP+4096)*4>>>();
    k4<<<4,256>>>(rescale);
    k4b<<<4,256>>>(wo);
    k5<<<512,128>>>(bo,out);
}

// round 8
// speedup vs baseline: 1.1450x; 1.1379x over previous
#include <cuda_runtime.h>
#include <math.h>

#define NPIX 16384
#define BN   65536   // 4 * 16384

typedef unsigned long long u64;

// ------------ scratch ------------------------------------------------------
__device__ float g_k[64*BN];
__device__ float g_v[64*BN];
__device__ float g_q[64*BN];
__device__ float g_xm[64*BN];
__device__ float g_Gpart[4*128*1024];
__device__ float g_sqp[4*128*64];
__device__ float g_skp[4*128*64];
__device__ float g_weffT[4*4096];
__device__ float g_wcatT[4096];
__device__ float g_wikT[4096];      // (in_w@wk)^T
__device__ float g_wivT[4096];      // (in_w@wv)^T
__device__ float g_wqT[4096];
__device__ float g_w1T[8192];
__device__ float g_w2T[16384];
__device__ float g_bcat[64];
__device__ float g_bik[64];         // in_b@wk + bk
__device__ float g_biv[64];         // in_b@wv + bv

// ------------ f32x2 helpers --------------------------------------------------
__device__ __forceinline__ u64 pack2(float lo, float hi){
    u64 r; asm("mov.b64 %0, {%1,%2};" : "=l"(r) : "f"(lo), "f"(hi)); return r;
}
__device__ __forceinline__ void unpack2(u64 a, float& lo, float& hi){
    asm("mov.b64 {%0,%1}, %2;" : "=f"(lo), "=f"(hi) : "l"(a));
}
__device__ __forceinline__ u64 fma2_(u64 a, u64 b, u64 c){
    u64 d; asm("fma.rn.f32x2 %0, %1, %2, %3;" : "=l"(d) : "l"(a), "l"(b), "l"(c)); return d;
}
__device__ __forceinline__ u64 add2_(u64 a, u64 b){
    u64 d; asm("add.rn.f32x2 %0, %1, %2;" : "=l"(d) : "l"(a), "l"(b)); return d;
}
__device__ __forceinline__ float hadd2(u64 a){
    float lo, hi; unpack2(a, lo, hi); return lo + hi;
}

__device__ __forceinline__ float dot64p(const float* w, const u64* xp){
    const ulonglong2* w2 = (const ulonglong2*)w;
    u64 a0=0ull,a1=0ull,a2=0ull,a3=0ull;
    #pragma unroll
    for (int i=0;i<8;i++){
        ulonglong2 wa=w2[2*i], wb=w2[2*i+1];
        a0=fma2_(xp[4*i+0], wa.x, a0);
        a1=fma2_(xp[4*i+1], wa.y, a1);
        a2=fma2_(xp[4*i+2], wb.x, a2);
        a3=fma2_(xp[4*i+3], wb.y, a3);
    }
    return hadd2(add2_(add2_(a0,a1),add2_(a2,a3)));
}
__device__ __forceinline__ float dot128p(const float* w, const u64* xp){
    const ulonglong2* w2 = (const ulonglong2*)w;
    u64 a0=0ull,a1=0ull,a2=0ull,a3=0ull;
    #pragma unroll
    for (int i=0;i<16;i++){
        ulonglong2 wa=w2[2*i], wb=w2[2*i+1];
        a0=fma2_(xp[4*i+0], wa.x, a0);
        a1=fma2_(xp[4*i+1], wa.y, a1);
        a2=fma2_(xp[4*i+2], wb.x, a2);
        a3=fma2_(xp[4*i+3], wb.y, a3);
    }
    return hadd2(add2_(add2_(a0,a1),add2_(a2,a3)));
}

// ------------ kprep: fold + transpose weights -------------------------------
__global__ void kprep(const float* wa, const float* ba, const float* wb, const float* bb,
                      const float* wq, const float* w1, const float* w2)
{
    int t = blockIdx.x*256 + threadIdx.x;     // 0..16383
    if (t < 4096) {
        int j = t>>6, c = t&63;
        float w;
        if (j < 4) w = wa[c*4 + j];
        else { int u=j-4; int kk=u/3; int d=u-kk*3; w = wb[kk*192 + c*3 + d]; }
        g_wcatT[t] = w;
        g_wqT[t]   = wq[c*64 + j];
    }
    if (t < 8192)  { int o=t>>6, c=t&63;  g_w1T[t] = w1[c*128 + o]; }
    if (t < 16384) { int o=t>>7, i=t&127; g_w2T[t] = w2[i*128 + o]; }
    if (t < 64) g_bcat[t] = (t < 4) ? ba[t] : bb[t-4];
}

// fold in_w into wk/wv: Wik = in_w @ wk  (transposed store)
__global__ void kfold(const float* inw, const float* inb,
                      const float* wk, const float* bk,
                      const float* wv, const float* bv)
{
    int t = blockIdx.x*256 + threadIdx.x;     // 0..8191
    int o = (t>>6)&63, c = t&63;
    const float* wx = (t < 4096) ? wk : wv;
    float acc = 0.f;
    #pragma unroll 4
    for (int m=0;m<64;m++) acc = fmaf(inw[c*64+m], wx[m*64+o], acc);
    if (t < 4096) g_wikT[o*64+c] = acc;
    else          g_wivT[o*64+c] = acc;
    if (t < 64) {
        float a=0.f, b2=0.f;
        for (int m=0;m<64;m++){ a=fmaf(inb[m],wk[m*64+t],a); b2=fmaf(inb[m],wv[m*64+t],b2); }
        g_bik[t] = a + bk[t];
        g_biv[t] = b2 + bv[t];
    }
}

// ------------ k1: feat path -> k, v (y folded away) --------------------------
// dyn smem floats: s_w 12288 | s_sem 5376 | s_bias 192 => 71424 B
__global__ void __launch_bounds__(256,1)
k1(const float* __restrict__ x, const float* __restrict__ sem)
{
    extern __shared__ float smx[];
    float* s_w    = smx;            // wcatT | wikT | wivT
    float* s_sem  = smx + 12288;
    float* s_bias = smx + 17664;
    int t = threadIdx.x;
    int gp = blockIdx.x*256 + t;
    int b = gp >> 14, p = gp & (NPIX-1);

    for (int i=t;i<4096;i+=256){
        s_w[i]      = g_wcatT[i];
        s_w[4096+i] = g_wikT[i];
        s_w[8192+i] = g_wivT[i];
    }
    if (t<64){ s_bias[t]=g_bcat[t]; s_bias[64+t]=g_bik[t]; s_bias[128+t]=g_biv[t]; }
    int sbase = b*21*NPIX + p;
    #pragma unroll
    for (int kk=0;kk<21;kk++){ float sv=sem[sbase+kk*NPIX]; s_sem[kk*256+t]=sv>0.f?sv:0.f; }

    u64 xp[32];
    int xbase = b*64*NPIX + p;
    #pragma unroll
    for (int c=0;c<64;c+=2) xp[c>>1]=pack2(x[xbase+c*NPIX], x[xbase+(c+1)*NPIX]);
    __syncthreads();

    // all_feat
    u64 ap[32];
    #pragma unroll 2
    for (int j=0;j<64;j+=2){
        float d0 = dot64p(s_w + j*64, xp);
        float d1 = dot64p(s_w + (j+1)*64, xp);
        int cls0 = (j   < 4) ? 0 : ((j-4)/3 + 1);
        int cls1 = (j+1 < 4) ? 0 : ((j-3)/3 + 1);
        float f0 = s_sem[cls0*256+t]*d0 + s_bias[j];
        float f1 = s_sem[cls1*256+t]*d1 + s_bias[j+1];
        ap[j>>1] = pack2(f0, f1);
    }
    // k = all_feat @ Wik + bik ;  v = all_feat @ Wiv + biv
    #pragma unroll 2
    for (int o=0;o<64;o++) g_k[o*BN+gp] = dot64p(s_w + 4096 + o*64, ap) + s_bias[64+o];
    #pragma unroll 2
    for (int o=0;o<64;o++) g_v[o*BN+gp] = dot64p(s_w + 8192 + o*64, ap) + s_bias[128+o];
}

// ------------ k2: LN-MLP -> xm, q (champion config) --------------------------
// dyn smem: wbuf 16384 f | hbuf 16384 u64 | s_p 896 f -> 200192 B
__global__ void __launch_bounds__(256,1)
k2(const float* __restrict__ x,
   const float* __restrict__ b1, const float* __restrict__ gm1, const float* __restrict__ be1,
   const float* __restrict__ b2, const float* __restrict__ gm2, const float* __restrict__ be2,
   const float* __restrict__ w3, const float* __restrict__ b3, const float* __restrict__ bq)
{
    extern __shared__ float smx[];
    float* wbuf = smx;                    // 16384
    u64*   hbuf = (u64*)(smx + 16384);    // 16384 u64
    float* s_p  = smx + 49152;            // 896
    int t = threadIdx.x;
    int gp = blockIdx.x*256 + t;
    int b = gp >> 14, p = gp & (NPIX-1);
    for (int i=t;i<128;i+=256){
        s_p[i]=b1[i]; s_p[128+i]=gm1[i]; s_p[256+i]=be1[i];
        s_p[384+i]=b2[i]; s_p[512+i]=gm2[i]; s_p[640+i]=be2[i];
    }
    if (t<64){ s_p[768+t]=b3[t]; s_p[832+t]=bq[t]; }
    for (int i=t;i<8192;i+=256) wbuf[i]=g_w1T[i];

    u64 xp[32];
    int xbase = b*64*NPIX + p;
    #pragma unroll
    for (int c=0;c<64;c+=2) xp[c>>1]=pack2(x[xbase+c*NPIX], x[xbase+(c+1)*NPIX]);
    __syncthreads();

    // layer 1
    u64 sp=0ull, s2p=0ull;
    #pragma unroll 2
    for (int o=0;o<128;o+=2){
        float u0 = dot64p(wbuf + o*64, xp) + s_p[o];
        float u1 = dot64p(wbuf + (o+1)*64, xp) + s_p[o+1];
        u64 up = pack2(u0,u1);
        hbuf[(o>>1)*256 + t] = up;
        sp = add2_(sp, up);
        s2p = fma2_(up, up, s2p);
    }
    float s = hadd2(sp), s2 = hadd2(s2p);
    float m = s*(1.f/128.f), var = s2*(1.f/128.f)-m*m, rinv = rsqrtf(var+1e-5f);

    u64 hp[64];
    #pragma unroll
    for (int i=0;i<64;i++){
        float u0,u1; unpack2(hbuf[i*256+t], u0, u1);
        float v0=(u0-m)*rinv*s_p[128+2*i]+s_p[256+2*i];
        float v1=(u1-m)*rinv*s_p[128+2*i+1]+s_p[256+2*i+1];
        v0 = v0>0.f?v0:0.01f*v0;
        v1 = v1>0.f?v1:0.01f*v1;
        hp[i]=pack2(v0,v1);
    }
    __syncthreads();
    for (int i=t;i<16384;i+=256) wbuf[i]=g_w2T[i];
    __syncthreads();

    // layer 2
    sp=0ull; s2p=0ull;
    #pragma unroll 2
    for (int o=0;o<128;o+=2){
        float u0 = dot128p(wbuf + o*128, hp) + s_p[384+o];
        float u1 = dot128p(wbuf + (o+1)*128, hp) + s_p[384+o+1];
        u64 up = pack2(u0,u1);
        hbuf[(o>>1)*256 + t] = up;
        sp = add2_(sp, up);
        s2p = fma2_(up, up, s2p);
    }
    s = hadd2(sp); s2 = hadd2(s2p);
    m = s*(1.f/128.f); var = s2*(1.f/128.f)-m*m; rinv = rsqrtf(var+1e-5f);

    __syncthreads();
    for (int i=t;i<8192;i+=256) wbuf[i]=w3[i];
    for (int i=t;i<4096;i+=256) wbuf[8192+i]=g_wqT[i];
    __syncthreads();

    // layer 3: xm
    u64 xmp[32];
    #pragma unroll
    for (int c=0;c<64;c+=2) xmp[c>>1] = pack2(s_p[768+c], s_p[768+c+1]);
    #pragma unroll 2
    for (int i=0;i<128;i+=2){
        float u0,u1; unpack2(hbuf[(i>>1)*256+t], u0, u1);
        float v0=(u0-m)*rinv*s_p[512+i]+s_p[640+i];
        float v1=(u1-m)*rinv*s_p[512+i+1]+s_p[640+i+1];
        v0 = v0>0.f?v0:0.01f*v0;
        v1 = v1>0.f?v1:0.01f*v1;
        u64 vv0=pack2(v0,v0), vv1=pack2(v1,v1);
        const ulonglong2* w0=(const ulonglong2*)(wbuf + i*64);
        const ulonglong2* w1p=(const ulonglong2*)(wbuf + (i+1)*64);
        #pragma unroll
        for (int c2=0;c2<16;c2++){
            ulonglong2 wa=w0[c2], wb=w1p[c2];
            xmp[2*c2+0]=fma2_(vv0, wa.x, xmp[2*c2+0]);
            xmp[2*c2+1]=fma2_(vv0, wa.y, xmp[2*c2+1]);
            xmp[2*c2+0]=fma2_(vv1, wb.x, xmp[2*c2+0]);
            xmp[2*c2+1]=fma2_(vv1, wb.y, xmp[2*c2+1]);
        }
    }
    #pragma unroll
    for (int c=0;c<64;c+=2){
        float v0,v1; unpack2(xmp[c>>1], v0, v1);
        g_xm[c*BN+gp]=v0; g_xm[(c+1)*BN+gp]=v1;
    }
    // q
    #pragma unroll 2
    for (int j=0;j<64;j++)
        g_q[j*BN+gp] = dot64p(wbuf + 8192 + j*64, xmp) + s_p[832+j];
}

// ------------ k3: Gram + norm partials per 128-pixel chunk -------------------
#define CHUNK 128
#define TP 129
__global__ void __launch_bounds__(256,2) k3()
{
    extern __shared__ float smx[];
    float* qs  = smx;             // 64*129
    float* ks  = smx + 64*TP;     // 64*129
    float* red = smx + 128*TP;    // 4096
    int t = threadIdx.x;
    int chunk = blockIdx.x, b = blockIdx.y;
    int pbase = b*NPIX + chunk*CHUNK;
    for (int i=t; i<64*CHUNK; i+=256){
        int ch=i>>7, pp=i&(CHUNK-1);
        qs[ch*TP+pp]=g_q[ch*BN+pbase+pp];
        ks[ch*TP+pp]=g_k[ch*BN+pbase+pp];
    }
    __syncthreads();
    int sub=t>>6, combo=t&63;
    int h=combo>>4, d4=(combo>>2)&3, e4=combo&3;
    const float* qsb=qs+(h*16+d4*4)*TP;
    const float* ksb=ks+(h*16+e4*4)*TP;
    float acc[4][4];
    #pragma unroll
    for (int i=0;i<4;i++)
        #pragma unroll
        for (int j=0;j<4;j++) acc[i][j]=0.f;
    for (int pp=sub*32; pp<sub*32+32; pp++){
        float q0=qsb[pp],q1=qsb[TP+pp],q2=qsb[2*TP+pp],q3=qsb[3*TP+pp];
        float k0=ksb[pp],k1v=ksb[TP+pp],k2v=ksb[2*TP+pp],k3v=ksb[3*TP+pp];
        acc[0][0]=fmaf(q0,k0,acc[0][0]); acc[0][1]=fmaf(q0,k1v,acc[0][1]); acc[0][2]=fmaf(q0,k2v,acc[0][2]); acc[0][3]=fmaf(q0,k3v,acc[0][3]);
        acc[1][0]=fmaf(q1,k0,acc[1][0]); acc[1][1]=fmaf(q1,k1v,acc[1][1]); acc[1][2]=fmaf(q1,k2v,acc[1][2]); acc[1][3]=fmaf(q1,k3v,acc[1][3]);
        acc[2][0]=fmaf(q2,k0,acc[2][0]); acc[2][1]=fmaf(q2,k1v,acc[2][1]); acc[2][2]=fmaf(q2,k2v,acc[2][2]); acc[2][3]=fmaf(q2,k3v,acc[2][3]);
        acc[3][0]=fmaf(q3,k0,acc[3][0]); acc[3][1]=fmaf(q3,k1v,acc[3][1]); acc[3][2]=fmaf(q3,k2v,acc[3][2]); acc[3][3]=fmaf(q3,k3v,acc[3][3]);
    }
    #pragma unroll
    for (int i=0;i<4;i++)
        #pragma unroll
        for (int j=0;j<4;j++)
            red[sub*1024 + (h*16+d4*4+i)*16 + (e4*4+j)] = acc[i][j];
    if (t < 64){
        const float* qr=qs+t*TP;
        float a0=0,a1=0,a2=0,a3=0;
        for (int pp=0;pp<CHUNK;pp+=4){
            a0=fmaf(qr[pp+0],qr[pp+0],a0); a1=fmaf(qr[pp+1],qr[pp+1],a1);
            a2=fmaf(qr[pp+2],qr[pp+2],a2); a3=fmaf(qr[pp+3],qr[pp+3],a3);
        }
        g_sqp[(b*128+chunk)*64+t]=(a0+a1)+(a2+a3);
    } else if (t < 128){
        int ch=t-64;
        const float* kr=ks+ch*TP;
        float a0=0,a1=0,a2=0,a3=0;
        for (int pp=0;pp<CHUNK;pp+=4){
            a0=fmaf(kr[pp+0],kr[pp+0],a0); a1=fmaf(kr[pp+1],kr[pp+1],a1);
            a2=fmaf(kr[pp+2],kr[pp+2],a2); a3=fmaf(kr[pp+3],kr[pp+3],a3);
        }
        g_skp[(b*128+chunk)*64+ch]=(a0+a1)+(a2+a3);
    }
    __syncthreads();
    float* gout = g_Gpart + (b*128+chunk)*1024;
    for (int idx=t; idx<1024; idx+=256)
        gout[idx] = (red[idx]+red[1024+idx]) + (red[2048+idx]+red[3072+idx]);
}

// ------------ k4: reduce + softmax + fold A into wo --------------------------
__global__ void k4(const float* __restrict__ rescale, const float* __restrict__ wo)
{
    __shared__ float sG[1024];
    __shared__ float snq[64], snk[64];
    __shared__ float sA[1024];
    __shared__ float swo[4096];
    int b=blockIdx.x, t=threadIdx.x;
    {
        float a0=0.f,a1=0.f,a2=0.f,a3=0.f;
        for (int c=0;c<128;c++){
            const float4 v = ((const float4*)(g_Gpart+(b*128+c)*1024))[t];
            a0+=v.x; a1+=v.y; a2+=v.z; a3+=v.w;
        }
        sG[t*4+0]=a0; sG[t*4+1]=a1; sG[t*4+2]=a2; sG[t*4+3]=a3;
    }
    if (t<64){
        float aq=0.f, ak=0.f;
        for (int c=0;c<128;c++){ aq+=g_sqp[(b*128+c)*64+t]; ak+=g_skp[(b*128+c)*64+t]; }
        snq[t]=sqrtf(aq)+1e-8f; snk[t]=sqrtf(ak)+1e-8f;
    }
    for (int i=t;i<4096;i+=256) swo[i]=wo[i];
    __syncthreads();
    if (t<64){
        int h=t>>4;
        float r=rescale[h], nq=snq[t];
        float ev[16]; float mx=-1e30f;
        #pragma unroll
        for (int e=0;e<16;e++){ ev[e]=sG[t*16+e]/(nq*snk[h*16+e])*r; mx=fmaxf(mx,ev[e]); }
        float ss=0.f;
        #pragma unroll
        for (int e=0;e<16;e++){ ev[e]=expf(ev[e]-mx); ss+=ev[e]; }
        float inv=1.f/ss;
        #pragma unroll
        for (int e=0;e<16;e++) sA[t*16+e]=ev[e]*inv;
    }
    __syncthreads();
    for (int idx=t; idx<4096; idx+=256){
        int cp=idx>>6, e=idx&63, h=e>>4, e15=e&15;
        float acc=0.f;
        #pragma unroll
        for (int d=0;d<16;d++)
            acc = fmaf(sA[h*256 + d*16 + e15], swo[(h*16+d)*64 + cp], acc);
        g_weffT[b*4096 + cp*64 + e] = acc;
    }
}

// ------------ k5: out = v @ WeffT + bo + xm ----------------------------------
__global__ void __launch_bounds__(256,2)
k5(const float* __restrict__ bo, float* __restrict__ out)
{
    __shared__ __align__(16) float sw[4096];
    __shared__ float sbo[64];
    int t=threadIdx.x;
    int gp=blockIdx.x*256+t;
    int b=gp>>14, p=gp&(NPIX-1);
    for (int i=t;i<4096;i+=256) sw[i]=g_weffT[b*4096+i];
    if (t<64) sbo[t]=bo[t];
    u64 vp[32];
    #pragma unroll
    for (int e=0;e<64;e+=2) vp[e>>1]=pack2(g_v[e*BN+gp], g_v[(e+1)*BN+gp]);
    __syncthreads();
    #pragma unroll 2
    for (int cp=0;cp<64;cp++){
        float d = dot64p(sw+cp*64, vp) + sbo[cp] + g_xm[cp*BN+gp];
        out[(size_t)(b*64+cp)*NPIX + p] = d;
    }
}

// ------------ launch ----------------------------------------------------------
extern "C" void kernel_launch(void* const* d_in, const int* in_sizes, int n_in,
                              void* d_out, int out_size)
{
    const float* x   =(const float*)d_in[0];
    const float* sem =(const float*)d_in[1];
    const float* wa  =(const float*)d_in[2];
    const float* ba  =(const float*)d_in[3];
    const float* wb  =(const float*)d_in[4];
    const float* bb  =(const float*)d_in[5];
    const float* inw =(const float*)d_in[6];
    const float* inb =(const float*)d_in[7];
    const float* w1  =(const float*)d_in[8];
    const float* b1  =(const float*)d_in[9];
    const float* gm1 =(const float*)d_in[10];
    const float* be1 =(const float*)d_in[11];
    const float* w2  =(const float*)d_in[12];
    const float* b2  =(const float*)d_in[13];
    const float* gm2 =(const float*)d_in[14];
    const float* be2 =(const float*)d_in[15];
    const float* w3  =(const float*)d_in[16];
    const float* b3  =(const float*)d_in[17];
    const float* wq  =(const float*)d_in[18];
    const float* bq  =(const float*)d_in[19];
    const float* wk  =(const float*)d_in[20];
    const float* bk  =(const float*)d_in[21];
    const float* wv  =(const float*)d_in[22];
    const float* bv  =(const float*)d_in[23];
    const float* wo  =(const float*)d_in[24];
    const float* bo  =(const float*)d_in[25];
    const float* rescale=(const float*)d_in[26];
    float* out=(float*)d_out;

    cudaFuncSetAttribute(k1, cudaFuncAttributeMaxDynamicSharedMemorySize, 17856*4);
    cudaFuncSetAttribute(k2, cudaFuncAttributeMaxDynamicSharedMemorySize, 50048*4);
    cudaFuncSetAttribute(k3, cudaFuncAttributeMaxDynamicSharedMemorySize, (128*TP+4096)*4);

    kprep<<<64,256>>>(wa,ba,wb,bb,wq,w1,w2);
    kfold<<<32,256>>>(inw,inb,wk,bk,wv,bv);
    k1<<<256,256,17856*4>>>(x,sem);
    k2<<<256,256,50048*4>>>(x,b1,gm1,be1,b2,gm2,be2,w3,b3,bq);
    k3<<<dim3(128,4),256,(128*TP+4096)*4>>>();
    k4<<<4,256>>>(rescale,wo);
    k5<<<256,256>>>(bo,out);
}